// round 14
// baseline (speedup 1.0000x reference)
#include <cuda_runtime.h>
#include <cuda_bf16.h>
#include <cstdint>

#define B_   4
#define T_   4096
#define D_   2048
#define MT_  16384                 // B_*T_
#define MTD_ 33554432              // MT_*D_ = 2^25
#define KDIM 2048
#define NDIM 2048
#define WSZ  4194304               // D_*D_ = 2^22
#define BM   128
#define BN   128
#define BK   32
#define PADK 40                    // padded smem row (bf16): 80B stride
#define STAGES 4
#define TILEE (BM * PADK)          // elements per As/Bs stage = 5120
#define SMEM_GEMM (STAGES * 2 * TILEE * 2)   // 81920 bytes

// ---------------- scratch (static device globals) ----------------
__device__ __align__(16) float         g_p[MTD_];    // wkv out
__device__ __align__(16) float         g_k[MTD_];
__device__ __align__(16) float         g_v[MTD_];
__device__ __align__(16) float         g_r[MTD_];
__device__ __align__(16) __nv_bfloat16 g_ahi[MTD_];  // activation hi (mix plane / rwkv)
__device__ __align__(16) __nv_bfloat16 g_alo[MTD_];  // activation lo
__device__ __align__(16) __nv_bfloat16 g_whi[WSZ];   // current weight hi
__device__ __align__(16) __nv_bfloat16 g_wlo[WSZ];   // current weight lo

// ---------------- helpers (proven) ----------------
__device__ __forceinline__ void splitf(float a, __nv_bfloat16& h, __nv_bfloat16& l) {
    __nv_bfloat16 hh = __float2bfloat16(a);
    h = hh;
    l = __float2bfloat16(a - __bfloat162float(hh));
}
__device__ __forceinline__ void cp16(void* smem, const void* g) {
    unsigned sa = (unsigned)__cvta_generic_to_shared(smem);
    asm volatile("cp.async.cg.shared.global [%0], [%1], 16;\n" :: "r"(sa), "l"(g));
}
__device__ __forceinline__ void cp_commit() { asm volatile("cp.async.commit_group;\n"); }
__device__ __forceinline__ void ldsm4(uint32_t r[4], const __nv_bfloat16* p) {
    unsigned a = (unsigned)__cvta_generic_to_shared(p);
    asm volatile("ldmatrix.sync.aligned.m8n8.x4.shared.b16 {%0,%1,%2,%3}, [%4];\n"
                 : "=r"(r[0]), "=r"(r[1]), "=r"(r[2]), "=r"(r[3]) : "r"(a));
}
__device__ __forceinline__ void mma_bf16(float c[4], const uint32_t a[4], const uint32_t b[2]) {
    asm volatile("mma.sync.aligned.m16n8k16.row.col.f32.bf16.bf16.f32 "
                 "{%0,%1,%2,%3},{%4,%5,%6,%7},{%8,%9},{%0,%1,%2,%3};\n"
                 : "+f"(c[0]), "+f"(c[1]), "+f"(c[2]), "+f"(c[3])
                 : "r"(a[0]), "r"(a[1]), "r"(a[2]), "r"(a[3]), "r"(b[0]), "r"(b[1]));
}

// ---------------- weight split: W (clamped scalar reads) -> g_whi/g_wlo ----------------
__global__ void __launch_bounds__(256) prepw_kernel(const float* __restrict__ W, long long wsz)
{
    long long stride = (long long)gridDim.x * blockDim.x;
    for (long long i = (long long)blockIdx.x * blockDim.x + threadIdx.x;
         i < (long long)WSZ; i += stride) {
        long long ir = (i < wsz) ? i : 0;
        __nv_bfloat16 h, l;
        splitf(W[ir], h, l);
        g_whi[i] = h;
        g_wlo[i] = l;
    }
}

// ---------------- token-shift mixing (one plane) -> bf16 hi/lo ----------------
__global__ void __launch_bounds__(256) mixsplit_kernel(
    const float* __restrict__ x, const float* __restrict__ tm,
    long long nx, long long ntm)
{
    long long stride = (long long)gridDim.x * blockDim.x;
    for (long long idx = (long long)blockIdx.x * blockDim.x + threadIdx.x;
         idx < (long long)MTD_; idx += stride) {
        int d = (int)(idx & (D_ - 1));
        int t = (int)((idx >> 11) & (T_ - 1));
        long long ix = (idx < nx) ? idx : 0;
        float xc = x[ix];
        float xs = 0.f;
        if (t != 0) {
            long long is = ix - D_;
            if (is < 0) is = 0;
            xs = x[is];
        }
        long long itm = (d < ntm) ? d : 0;
        float m = xs + tm[itm] * (xc - xs);
        __nv_bfloat16 h, l;
        splitf(m, h, l);
        g_ahi[idx] = h;
        g_alo[idx] = l;
    }
}

// ---------------- 3-pass split-bf16 mma GEMM, 64x64 warp tiles, 4-stage pipeline ------
// C[M,N] = sum_d A[m,d] * W[n,d];  pass0 Ahi*Bhi, pass1 Alo*Bhi, pass2 Ahi*Blo
// 128 threads = 4 warps in 2x2; each warp computes 64x64 of the 128x128 CTA tile.
__global__ void __launch_bounds__(128) gemm3p_kernel(
    const __nv_bfloat16* __restrict__ Ahi, const __nv_bfloat16* __restrict__ Alo,
    const __nv_bfloat16* __restrict__ Bhi, const __nv_bfloat16* __restrict__ Blo,
    float* __restrict__ C)
{
    extern __shared__ __nv_bfloat16 sm[];
    __nv_bfloat16* As = sm;                       // STAGES * TILEE
    __nv_bfloat16* Bs = sm + STAGES * TILEE;      // STAGES * TILEE
    const int tid = threadIdx.x, lane = tid & 31, warp = tid >> 5;
    const int bm = blockIdx.y * BM, bn = blockIdx.x * BN;   // N-fastest
    const int wmo = (warp & 1) * 64, wno = (warp >> 1) * 64;
    const int lr = tid >> 2, lc = (tid & 3) * 8;   // fill: 32 rows/pass, 4 passes

    float acc[4][8][4];
    #pragma unroll
    for (int i = 0; i < 4; i++)
        #pragma unroll
        for (int j = 0; j < 8; j++)
            #pragma unroll
            for (int q = 0; q < 4; q++) acc[i][j][q] = 0.f;

    const int NIT = 3 * (KDIM / BK);  // 192

    #define FILL(slot, it_) do {                                                   \
        int p_  = (it_) >> 6;                                                      \
        int k0_ = ((it_) & 63) * BK;                                               \
        const __nv_bfloat16* A_  = (p_ == 1) ? Alo : Ahi;                          \
        const __nv_bfloat16* Bt_ = (p_ == 2) ? Blo : Bhi;                          \
        __nv_bfloat16* as_ = As + (slot) * TILEE;                                  \
        __nv_bfloat16* bs_ = Bs + (slot) * TILEE;                                  \
        _Pragma("unroll")                                                          \
        for (int i_ = 0; i_ < 4; i_++) {                                           \
            int r_ = lr + i_ * 32;                                                 \
            cp16(&as_[r_ * PADK + lc], A_  + (size_t)(bm + r_) * KDIM + k0_ + lc); \
            cp16(&bs_[r_ * PADK + lc], Bt_ + (size_t)(bn + r_) * KDIM + k0_ + lc); \
        }                                                                          \
        cp_commit();                                                               \
    } while (0)

    // prologue: stages 0..2 in flight
    FILL(0, 0);
    FILL(1, 1);
    FILL(2, 2);

    for (int it = 0; it < NIT; it++) {
        if (it < NIT - 2)       asm volatile("cp.async.wait_group 2;\n");
        else if (it == NIT - 2) asm volatile("cp.async.wait_group 1;\n");
        else                    asm volatile("cp.async.wait_group 0;\n");
        __syncthreads();
        if (it + 3 < NIT) FILL((it + 3) & 3, it + 3);

        const __nv_bfloat16* as = As + (it & 3) * TILEE;
        const __nv_bfloat16* bs = Bs + (it & 3) * TILEE;
        #pragma unroll
        for (int ks = 0; ks < 2; ks++) {
            uint32_t a[4][4];
            #pragma unroll
            for (int mi = 0; mi < 4; mi++)
                ldsm4(a[mi], &as[(wmo + mi * 16 + (lane & 15)) * PADK + ks * 16 + (lane >> 4) * 8]);
            uint32_t b[8][2];
            #pragma unroll
            for (int nj = 0; nj < 4; nj++) {
                uint32_t r4[4];
                ldsm4(r4, &bs[(wno + nj * 16 + (lane & 7) + ((lane >> 4) << 3)) * PADK
                              + ks * 16 + (((lane >> 3) & 1) << 3)]);
                b[nj * 2][0] = r4[0]; b[nj * 2][1] = r4[1];
                b[nj * 2 + 1][0] = r4[2]; b[nj * 2 + 1][1] = r4[3];
            }
            #pragma unroll
            for (int mi = 0; mi < 4; mi++)
                #pragma unroll
                for (int ni = 0; ni < 8; ni++)
                    mma_bf16(acc[mi][ni], a[mi], b[ni]);
        }
    }
    #undef FILL

    #pragma unroll
    for (int mi = 0; mi < 4; mi++) {
        int row = bm + wmo + mi * 16 + (lane >> 2);
        #pragma unroll
        for (int ni = 0; ni < 8; ni++) {
            int col = bn + wno + ni * 8 + (lane & 3) * 2;
            *(float2*)(C + (size_t)row * NDIM + col)       = make_float2(acc[mi][ni][0], acc[mi][ni][1]);
            *(float2*)(C + (size_t)(row + 8) * NDIM + col) = make_float2(acc[mi][ni][2], acc[mi][ni][3]);
        }
    }
}

// ---------------- WKV, closed decay-free form, global channel pivot (proven) ----------
__global__ void __launch_bounds__(32) wkv2_kernel(
    const float* __restrict__ kin, const float* __restrict__ vin,
    const float* __restrict__ td, const float* __restrict__ tf,
    float* __restrict__ outp, long long nvec)
{
    int idx = blockIdx.x * 32 + threadIdx.x;    // 256 blocks x 32 = 8192 channels
    int b = idx >> 11, d = idx & (D_ - 1);
    long long iv = (d < nvec) ? d : 0;
    (void)td;                                    // decay cancels exactly
    const float u = tf[iv];
    size_t base = ((size_t)b * T_) * D_ + d;

    float kmax = -1e30f;
    for (int t = 0; t < T_; t += 4) {
        float m0 = kin[base + (size_t)(t + 0) * D_];
        float m1 = kin[base + (size_t)(t + 1) * D_];
        float m2 = kin[base + (size_t)(t + 2) * D_];
        float m3 = kin[base + (size_t)(t + 3) * D_];
        kmax = fmaxf(kmax, fmaxf(fmaxf(m0, m1), fmaxf(m2, m3)));
    }
    float sa = 0.f, sb = 0.f;
    for (int t = 0; t < T_; t++) {
        float kt = kin[base + (size_t)t * D_];
        float vt = vin[base + (size_t)t * D_];
        float ecur = __expf(kt + u - kmax);
        outp[base + (size_t)t * D_] = __fdividef(fmaf(ecur, vt, sa), sb + ecur);
        float e = __expf(kt - kmax);
        sa = fmaf(e, vt, sa);
        sb += e;
    }
}

// ---------------- LayerNorm (two-pass) * sigmoid(r) -> bf16 hi/lo ----------------
__global__ void __launch_bounds__(256) ln2split_kernel(
    const float* __restrict__ wkv, const float* __restrict__ rlin,
    const float* __restrict__ gam, const float* __restrict__ bet,
    long long nvec)
{
    __shared__ float red[8];
    int row = blockIdx.x, tid = threadIdx.x;
    const float* wp = wkv + (size_t)row * D_;
    float xx[8], rr[8];
    #pragma unroll
    for (int i = 0; i < 8; i++) {
        xx[i] = wp[tid + i * 256];
        rr[i] = rlin[(size_t)row * D_ + tid + i * 256];
    }
    float s = 0.f;
    #pragma unroll
    for (int i = 0; i < 8; i++) s += xx[i];
    #pragma unroll
    for (int o = 16; o; o >>= 1) s += __shfl_xor_sync(0xffffffffu, s, o);
    if ((tid & 31) == 0) red[tid >> 5] = s;
    __syncthreads();
    if (tid == 0) {
        float a = 0.f;
        #pragma unroll
        for (int i = 0; i < 8; i++) a += red[i];
        red[0] = a;
    }
    __syncthreads();
    float mean = red[0] * (1.0f / D_);
    __syncthreads();
    float ss = 0.f;
    #pragma unroll
    for (int i = 0; i < 8; i++) {
        float dv = xx[i] - mean;
        ss = fmaf(dv, dv, ss);
    }
    #pragma unroll
    for (int o = 16; o; o >>= 1) ss += __shfl_xor_sync(0xffffffffu, ss, o);
    if ((tid & 31) == 0) red[tid >> 5] = ss;
    __syncthreads();
    if (tid == 0) {
        float a = 0.f;
        #pragma unroll
        for (int i = 0; i < 8; i++) a += red[i];
        red[0] = a;
    }
    __syncthreads();
    float var = red[0] * (1.0f / D_);
    float rs  = rsqrtf(var + 1e-5f);
    #pragma unroll
    for (int i = 0; i < 8; i++) {
        int col = tid + i * 256;
        long long ic = (col < nvec) ? col : 0;
        float ln = (xx[i] - mean) * rs * gam[ic] + bet[ic];
        float sg = __fdividef(1.f, 1.f + __expf(-rr[i]));
        __nv_bfloat16 h, l;
        splitf(sg * ln, h, l);
        g_ahi[(size_t)row * D_ + col] = h;
        g_alo[(size_t)row * D_ + col] = l;
    }
}

// ---------------- host launcher ----------------
extern "C" void kernel_launch(void* const* d_in, const int* in_sizes, int n_in,
                              void* d_out, int out_size)
{
    (void)out_size;
    const float* x = nullptr;
    const float* W[4]   = { nullptr, nullptr, nullptr, nullptr };
    const float* vec[7] = { nullptr, nullptr, nullptr, nullptr, nullptr, nullptr, nullptr };
    long long nx = MTD_, nw = WSZ, nv = D_;
    int wn = 0, vn = 0;
    for (int i = 0; i < n_in; i++) {
        long long s = in_sizes[i];
        if (s == (long long)MTD_)      { if (!x) { x = (const float*)d_in[i]; nx = s; } }
        else if (s == (long long)WSZ)  { if (wn < 4) { W[wn++] = (const float*)d_in[i]; nw = s; } }
        else if (s == (long long)D_)   { if (vn < 7) { vec[vn++] = (const float*)d_in[i]; nv = s; } }
    }
    if (!x || wn < 4 || vn < 7) {
        x = (const float*)d_in[0];
        for (int i = 0; i < 4; i++) W[i] = (const float*)d_in[1 + i];
        for (int i = 0; i < 7; i++) vec[i] = (const float*)d_in[5 + i];
        nx = MTD_; nw = WSZ; nv = D_;
    }
    const float *Wk = W[0], *Wv = W[1], *Wr = W[2], *Wo = W[3];
    const float *tmk = vec[0], *tmv = vec[1], *tmr = vec[2];
    const float *td  = vec[3], *tf  = vec[4];
    const float *lng = vec[5], *lnb = vec[6];
    float* out = (float*)d_out;

    float *p, *k, *v, *r;
    __nv_bfloat16 *ahi, *alo, *whi, *wlo;
    cudaGetSymbolAddress((void**)&p,   g_p);
    cudaGetSymbolAddress((void**)&k,   g_k);
    cudaGetSymbolAddress((void**)&v,   g_v);
    cudaGetSymbolAddress((void**)&r,   g_r);
    cudaGetSymbolAddress((void**)&ahi, g_ahi);
    cudaGetSymbolAddress((void**)&alo, g_alo);
    cudaGetSymbolAddress((void**)&whi, g_whi);
    cudaGetSymbolAddress((void**)&wlo, g_wlo);

    cudaFuncSetAttribute(gemm3p_kernel, cudaFuncAttributeMaxDynamicSharedMemorySize, SMEM_GEMM);

    dim3 gg(NDIM / BN, MT_ / BM);    // (16, 128): N-block fastest

    mixsplit_kernel<<<8192, 256>>>(x, tmk, nx, nv);
    prepw_kernel<<<4096, 256>>>(Wk, nw);
    gemm3p_kernel<<<gg, 128, SMEM_GEMM>>>(ahi, alo, whi, wlo, k);

    mixsplit_kernel<<<8192, 256>>>(x, tmv, nx, nv);
    prepw_kernel<<<4096, 256>>>(Wv, nw);
    gemm3p_kernel<<<gg, 128, SMEM_GEMM>>>(ahi, alo, whi, wlo, v);

    mixsplit_kernel<<<8192, 256>>>(x, tmr, nx, nv);
    prepw_kernel<<<4096, 256>>>(Wr, nw);
    gemm3p_kernel<<<gg, 128, SMEM_GEMM>>>(ahi, alo, whi, wlo, r);

    wkv2_kernel<<<256, 32>>>(k, v, td, tf, p, nv);
    ln2split_kernel<<<MT_, 256>>>(p, r, lng, lnb, nv);

    prepw_kernel<<<4096, 256>>>(Wo, nw);
    gemm3p_kernel<<<gg, 128, SMEM_GEMM>>>(ahi, alo, whi, wlo, out);
}

// round 17
// speedup vs baseline: 1.4323x; 1.4323x over previous
#include <cuda_runtime.h>
#include <cuda_fp16.h>
#include <cstdint>

#define B_   4
#define T_   4096
#define D_   2048
#define MT_  16384                 // B_*T_
#define MTD_ 33554432              // MT_*D_ = 2^25
#define KDIM 2048
#define NDIM 2048
#define WSZ  4194304               // D_*D_ = 2^22
#define BM   128
#define BN   128
#define BK   32
#define PADK 40                    // padded smem row (fp16): 80B stride
#define STAGES 4
#define TILEE (BM * PADK)          // elements per As/Bs stage = 5120
#define SMEM_GEMM (STAGES * 2 * TILEE * 2)   // 81920 bytes

// ---------------- scratch (static device globals) ----------------
__device__ __align__(16) float  g_p[MTD_];    // wkv out
__device__ __align__(16) float  g_k[MTD_];
__device__ __align__(16) float  g_v[MTD_];
__device__ __align__(16) float  g_r[MTD_];
__device__ __align__(16) __half g_ahi[MTD_];  // activation hi (mix plane / rwkv)
__device__ __align__(16) __half g_alo[MTD_];  // activation lo
__device__ __align__(16) __half g_whi[WSZ];   // current weight hi
__device__ __align__(16) __half g_wlo[WSZ];   // current weight lo (unused by 2-pass GEMM)

// ---------------- helpers (proven) ----------------
__device__ __forceinline__ void splitf(float a, __half& h, __half& l) {
    __half hh = __float2half(a);
    h = hh;
    l = __float2half(a - __half2float(hh));
}
__device__ __forceinline__ void cp16(void* smem, const void* g) {
    unsigned sa = (unsigned)__cvta_generic_to_shared(smem);
    asm volatile("cp.async.cg.shared.global [%0], [%1], 16;\n" :: "r"(sa), "l"(g));
}
__device__ __forceinline__ void cp_commit() { asm volatile("cp.async.commit_group;\n"); }
__device__ __forceinline__ void ldsm4(uint32_t r[4], const __half* p) {
    unsigned a = (unsigned)__cvta_generic_to_shared(p);
    asm volatile("ldmatrix.sync.aligned.m8n8.x4.shared.b16 {%0,%1,%2,%3}, [%4];\n"
                 : "=r"(r[0]), "=r"(r[1]), "=r"(r[2]), "=r"(r[3]) : "r"(a));
}
__device__ __forceinline__ void mma_bf16(float c[4], const uint32_t a[4], const uint32_t b[2]) {
    asm volatile("mma.sync.aligned.m16n8k16.row.col.f32.f16.f16.f32 "
                 "{%0,%1,%2,%3},{%4,%5,%6,%7},{%8,%9},{%0,%1,%2,%3};\n"
                 : "+f"(c[0]), "+f"(c[1]), "+f"(c[2]), "+f"(c[3])
                 : "r"(a[0]), "r"(a[1]), "r"(a[2]), "r"(a[3]), "r"(b[0]), "r"(b[1]));
}

// ---------------- weight split: W (clamped scalar reads) -> g_whi/g_wlo ----------------
__global__ void __launch_bounds__(256) prepw_kernel(const float* __restrict__ W, long long wsz)
{
    long long stride = (long long)gridDim.x * blockDim.x;
    for (long long i = (long long)blockIdx.x * blockDim.x + threadIdx.x;
         i < (long long)WSZ; i += stride) {
        long long ir = (i < wsz) ? i : 0;
        __half h, l;
        splitf(W[ir], h, l);
        g_whi[i] = h;
        g_wlo[i] = l;
    }
}

// ---------------- token-shift mixing (one plane) -> fp16 hi/lo ----------------
__global__ void __launch_bounds__(256) mixsplit_kernel(
    const float* __restrict__ x, const float* __restrict__ tm,
    long long nx, long long ntm)
{
    long long stride = (long long)gridDim.x * blockDim.x;
    for (long long idx = (long long)blockIdx.x * blockDim.x + threadIdx.x;
         idx < (long long)MTD_; idx += stride) {
        int d = (int)(idx & (D_ - 1));
        int t = (int)((idx >> 11) & (T_ - 1));
        long long ix = (idx < nx) ? idx : 0;
        float xc = x[ix];
        float xs = 0.f;
        if (t != 0) {
            long long is = ix - D_;
            if (is < 0) is = 0;
            xs = x[is];
        }
        long long itm = (d < ntm) ? d : 0;
        float m = xs + tm[itm] * (xc - xs);
        __half h, l;
        splitf(m, h, l);
        g_ahi[idx] = h;
        g_alo[idx] = l;
    }
}

// ---------------- 2-pass split-fp16 mma GEMM, 4-stage cp.async pipeline ----------------
// C[M,N] = sum_d A[m,d] * W[n,d];  pass0 Ahi*Bhi, pass1 Alo*Bhi  (pass2 path unused)
__global__ void __launch_bounds__(256) gemm3p_kernel(
    const __half* __restrict__ Ahi, const __half* __restrict__ Alo,
    const __half* __restrict__ Bhi, const __half* __restrict__ Blo,
    float* __restrict__ C)
{
    extern __shared__ __half sm[];
    __half* As = sm;                       // STAGES * TILEE
    __half* Bs = sm + STAGES * TILEE;      // STAGES * TILEE
    const int tid = threadIdx.x, lane = tid & 31, warp = tid >> 5;
    const int bm = blockIdx.y * BM, bn = blockIdx.x * BN;   // N-fastest
    const int wmo = (warp & 1) * 64, wno = (warp >> 1) * 32;
    const int lr = tid >> 2, lc = (tid & 3) * 8;

    float acc[4][4][4];
    #pragma unroll
    for (int i = 0; i < 4; i++)
        #pragma unroll
        for (int j = 0; j < 4; j++)
            #pragma unroll
            for (int q = 0; q < 4; q++) acc[i][j][q] = 0.f;

    const int NIT = 2 * (KDIM / BK);  // 128 (two passes)

    #define FILL(slot, it_) do {                                                   \
        int p_  = (it_) >> 6;                                                      \
        int k0_ = ((it_) & 63) * BK;                                               \
        const __half* A_  = (p_ == 1) ? Alo : Ahi;                                 \
        const __half* Bt_ = (p_ == 2) ? Blo : Bhi;                                 \
        __half* as_ = As + (slot) * TILEE;                                         \
        __half* bs_ = Bs + (slot) * TILEE;                                         \
        _Pragma("unroll")                                                          \
        for (int i_ = 0; i_ < 2; i_++) {                                           \
            int r_ = lr + i_ * 64;                                                 \
            cp16(&as_[r_ * PADK + lc], A_  + (size_t)(bm + r_) * KDIM + k0_ + lc); \
            cp16(&bs_[r_ * PADK + lc], Bt_ + (size_t)(bn + r_) * KDIM + k0_ + lc); \
        }                                                                          \
        cp_commit();                                                               \
    } while (0)

    // prologue: stages 0..2 in flight
    FILL(0, 0);
    FILL(1, 1);
    FILL(2, 2);

    for (int it = 0; it < NIT; it++) {
        if (it < NIT - 2)       asm volatile("cp.async.wait_group 2;\n");
        else if (it == NIT - 2) asm volatile("cp.async.wait_group 1;\n");
        else                    asm volatile("cp.async.wait_group 0;\n");
        __syncthreads();
        if (it + 3 < NIT) FILL((it + 3) & 3, it + 3);

        const __half* as = As + (it & 3) * TILEE;
        const __half* bs = Bs + (it & 3) * TILEE;
        #pragma unroll
        for (int ks = 0; ks < 2; ks++) {
            uint32_t a[4][4];
            #pragma unroll
            for (int mi = 0; mi < 4; mi++)
                ldsm4(a[mi], &as[(wmo + mi * 16 + (lane & 15)) * PADK + ks * 16 + (lane >> 4) * 8]);
            uint32_t b[4][2];
            #pragma unroll
            for (int nj = 0; nj < 2; nj++) {
                uint32_t r4[4];
                ldsm4(r4, &bs[(wno + nj * 16 + (lane & 7) + ((lane >> 4) << 3)) * PADK
                              + ks * 16 + (((lane >> 3) & 1) << 3)]);
                b[nj * 2][0] = r4[0]; b[nj * 2][1] = r4[1];
                b[nj * 2 + 1][0] = r4[2]; b[nj * 2 + 1][1] = r4[3];
            }
            #pragma unroll
            for (int mi = 0; mi < 4; mi++)
                #pragma unroll
                for (int ni = 0; ni < 4; ni++)
                    mma_bf16(acc[mi][ni], a[mi], b[ni]);
        }
    }
    #undef FILL

    #pragma unroll
    for (int mi = 0; mi < 4; mi++) {
        int row = bm + wmo + mi * 16 + (lane >> 2);
        #pragma unroll
        for (int ni = 0; ni < 4; ni++) {
            int col = bn + wno + ni * 8 + (lane & 3) * 2;
            *(float2*)(C + (size_t)row * NDIM + col)       = make_float2(acc[mi][ni][0], acc[mi][ni][1]);
            *(float2*)(C + (size_t)(row + 8) * NDIM + col) = make_float2(acc[mi][ni][2], acc[mi][ni][3]);
        }
    }
}

// ---------------- WKV, closed decay-free form, global channel pivot (R14-proven) ------
__global__ void __launch_bounds__(32) wkv2_kernel(
    const float* __restrict__ kin, const float* __restrict__ vin,
    const float* __restrict__ td, const float* __restrict__ tf,
    float* __restrict__ outp, long long nvec)
{
    int idx = blockIdx.x * 32 + threadIdx.x;    // 256 blocks x 32 = 8192 channels
    int b = idx >> 11, d = idx & (D_ - 1);
    long long iv = (d < nvec) ? d : 0;
    (void)td;                                    // decay cancels exactly
    const float u = tf[iv];
    size_t base = ((size_t)b * T_) * D_ + d;

    float kmax = -1e30f;
    for (int t = 0; t < T_; t += 4) {
        float m0 = kin[base + (size_t)(t + 0) * D_];
        float m1 = kin[base + (size_t)(t + 1) * D_];
        float m2 = kin[base + (size_t)(t + 2) * D_];
        float m3 = kin[base + (size_t)(t + 3) * D_];
        kmax = fmaxf(kmax, fmaxf(fmaxf(m0, m1), fmaxf(m2, m3)));
    }
    float sa = 0.f, sb = 0.f;
    for (int t = 0; t < T_; t++) {
        float kt = kin[base + (size_t)t * D_];
        float vt = vin[base + (size_t)t * D_];
        float ecur = __expf(kt + u - kmax);
        outp[base + (size_t)t * D_] = __fdividef(fmaf(ecur, vt, sa), sb + ecur);
        float e = __expf(kt - kmax);
        sa = fmaf(e, vt, sa);
        sb += e;
    }
}

// ---------------- LayerNorm (two-pass) * sigmoid(r) -> fp16 hi/lo ----------------
__global__ void __launch_bounds__(256) ln2split_kernel(
    const float* __restrict__ wkv, const float* __restrict__ rlin,
    const float* __restrict__ gam, const float* __restrict__ bet,
    long long nvec)
{
    __shared__ float red[8];
    int row = blockIdx.x, tid = threadIdx.x;
    const float* wp = wkv + (size_t)row * D_;
    float xx[8], rr[8];
    #pragma unroll
    for (int i = 0; i < 8; i++) {
        xx[i] = wp[tid + i * 256];
        rr[i] = rlin[(size_t)row * D_ + tid + i * 256];
    }
    float s = 0.f;
    #pragma unroll
    for (int i = 0; i < 8; i++) s += xx[i];
    #pragma unroll
    for (int o = 16; o; o >>= 1) s += __shfl_xor_sync(0xffffffffu, s, o);
    if ((tid & 31) == 0) red[tid >> 5] = s;
    __syncthreads();
    if (tid == 0) {
        float a = 0.f;
        #pragma unroll
        for (int i = 0; i < 8; i++) a += red[i];
        red[0] = a;
    }
    __syncthreads();
    float mean = red[0] * (1.0f / D_);
    __syncthreads();
    float ss = 0.f;
    #pragma unroll
    for (int i = 0; i < 8; i++) {
        float dv = xx[i] - mean;
        ss = fmaf(dv, dv, ss);
    }
    #pragma unroll
    for (int o = 16; o; o >>= 1) ss += __shfl_xor_sync(0xffffffffu, ss, o);
    if ((tid & 31) == 0) red[tid >> 5] = ss;
    __syncthreads();
    if (tid == 0) {
        float a = 0.f;
        #pragma unroll
        for (int i = 0; i < 8; i++) a += red[i];
        red[0] = a;
    }
    __syncthreads();
    float var = red[0] * (1.0f / D_);
    float rs  = rsqrtf(var + 1e-5f);
    #pragma unroll
    for (int i = 0; i < 8; i++) {
        int col = tid + i * 256;
        long long ic = (col < nvec) ? col : 0;
        float ln = (xx[i] - mean) * rs * gam[ic] + bet[ic];
        float sg = __fdividef(1.f, 1.f + __expf(-rr[i]));
        __half h, l;
        splitf(sg * ln, h, l);
        g_ahi[(size_t)row * D_ + col] = h;
        g_alo[(size_t)row * D_ + col] = l;
    }
}

// ---------------- host launcher ----------------
extern "C" void kernel_launch(void* const* d_in, const int* in_sizes, int n_in,
                              void* d_out, int out_size)
{
    (void)out_size;
    const float* x = nullptr;
    const float* W[4]   = { nullptr, nullptr, nullptr, nullptr };
    const float* vec[7] = { nullptr, nullptr, nullptr, nullptr, nullptr, nullptr, nullptr };
    long long nx = MTD_, nw = WSZ, nv = D_;
    int wn = 0, vn = 0;
    for (int i = 0; i < n_in; i++) {
        long long s = in_sizes[i];
        if (s == (long long)MTD_)      { if (!x) { x = (const float*)d_in[i]; nx = s; } }
        else if (s == (long long)WSZ)  { if (wn < 4) { W[wn++] = (const float*)d_in[i]; nw = s; } }
        else if (s == (long long)D_)   { if (vn < 7) { vec[vn++] = (const float*)d_in[i]; nv = s; } }
    }
    if (!x || wn < 4 || vn < 7) {
        x = (const float*)d_in[0];
        for (int i = 0; i < 4; i++) W[i] = (const float*)d_in[1 + i];
        for (int i = 0; i < 7; i++) vec[i] = (const float*)d_in[5 + i];
        nx = MTD_; nw = WSZ; nv = D_;
    }
    const float *Wk = W[0], *Wv = W[1], *Wr = W[2], *Wo = W[3];
    const float *tmk = vec[0], *tmv = vec[1], *tmr = vec[2];
    const float *td  = vec[3], *tf  = vec[4];
    const float *lng = vec[5], *lnb = vec[6];
    float* out = (float*)d_out;

    float *p, *k, *v, *r;
    __half *ahi, *alo, *whi, *wlo;
    cudaGetSymbolAddress((void**)&p,   g_p);
    cudaGetSymbolAddress((void**)&k,   g_k);
    cudaGetSymbolAddress((void**)&v,   g_v);
    cudaGetSymbolAddress((void**)&r,   g_r);
    cudaGetSymbolAddress((void**)&ahi, g_ahi);
    cudaGetSymbolAddress((void**)&alo, g_alo);
    cudaGetSymbolAddress((void**)&whi, g_whi);
    cudaGetSymbolAddress((void**)&wlo, g_wlo);

    cudaFuncSetAttribute(gemm3p_kernel, cudaFuncAttributeMaxDynamicSharedMemorySize, SMEM_GEMM);

    dim3 gg(NDIM / BN, MT_ / BM);    // (16, 128): N-block fastest

    mixsplit_kernel<<<8192, 256>>>(x, tmk, nx, nv);
    prepw_kernel<<<4096, 256>>>(Wk, nw);
    gemm3p_kernel<<<gg, 256, SMEM_GEMM>>>(ahi, alo, whi, wlo, k);

    mixsplit_kernel<<<8192, 256>>>(x, tmv, nx, nv);
    prepw_kernel<<<4096, 256>>>(Wv, nw);
    gemm3p_kernel<<<gg, 256, SMEM_GEMM>>>(ahi, alo, whi, wlo, v);

    mixsplit_kernel<<<8192, 256>>>(x, tmr, nx, nv);
    prepw_kernel<<<4096, 256>>>(Wr, nw);
    gemm3p_kernel<<<gg, 256, SMEM_GEMM>>>(ahi, alo, whi, wlo, r);

    wkv2_kernel<<<256, 32>>>(k, v, td, tf, p, nv);
    ln2split_kernel<<<MT_, 256>>>(p, r, lng, lnb, nv);

    prepw_kernel<<<4096, 256>>>(Wo, nw);
    gemm3p_kernel<<<gg, 256, SMEM_GEMM>>>(ahi, alo, whi, wlo, out);
}